// round 13
// baseline (speedup 1.0000x reference)
#include <cuda_runtime.h>
#include <cuda_bf16.h>
#include <math.h>

#define BB 64
#define LL 384
#define CC 512
#define HH 512
#define EE 256
#define NC 250
#define TT 127
#define KX 1280     // C + E + H
#define G4 2048     // 4*H
#define KSPLIT 16
#define KSLICE 80   // KX / KSPLIT
#define NBLK 256    // persistent grid size

// ---------------- device scratch ----------------
__device__ __align__(16) float g_srcfT[(size_t)BB * HH * LL];   // [b][h][l]
__device__ __align__(16) float g_Wt[(size_t)KX * G4];           // [k][u*4+g]
__device__ __align__(16) float g_bperm[G4];
__device__ __align__(16) float g_WgenT[HH * NC];                // [k][n]
__device__ __align__(16) float g_embT[(size_t)TT * EE * BB];    // [t][e][b]
__device__ __align__(16) float g_h[BB * HH];                    // [b][u]
__device__ __align__(16) float g_hT[HH * BB];                   // [u][b]
__device__ __align__(16) float g_cT[HH * BB];                   // [u][b]
__device__ __align__(16) float g_proj[BB * HH];
__device__ __align__(16) float g_lgp[4 * BB * LL];              // score partials
__device__ __align__(16) float g_X[CC * BB];                    // context transposed [c][b]
__device__ __align__(16) float g_gp[(size_t)KSPLIT * G4 * BB];  // gate partials
__device__ __align__(16) float g_hs[(size_t)BB * TT * HH];

// grid barrier state (self-restoring: count returns to 0, gen monotonic)
__device__ unsigned g_cnt = 0;
__device__ unsigned g_gen = 0;

// ---------------- math ----------------
__device__ __forceinline__ float tanh_fast(float x) {
    float y;
    asm("tanh.approx.f32 %0, %1;" : "=f"(y) : "f"(x));
    return y;
}
__device__ __forceinline__ float tanh_acc(float x) {
    float a = fabsf(x);
    float e = __expf(-2.0f * a);
    float r = __fdividef(1.0f - e, 1.0f + e);
    return copysignf(r, x);
}
__device__ __forceinline__ float sigm(float x) {
    return __fdividef(1.0f, 1.0f + __expf(-x));
}

// software grid barrier (all NBLK CTAs co-resident via __launch_bounds__ min-blocks)
__device__ __forceinline__ void gsync() {
    __syncthreads();
    if (threadIdx.x == 0) {
        unsigned gen = *((volatile unsigned*)&g_gen);
        __threadfence();
        unsigned old = atomicAdd(&g_cnt, 1u);
        if (old == (unsigned)(gridDim.x - 1)) {
            *((volatile unsigned*)&g_cnt) = 0u;
            __threadfence();
            atomicAdd(&g_gen, 1u);
        } else {
            while (*((volatile unsigned*)&g_gen) == gen) { __nanosleep(64); }
            __threadfence();
        }
    }
    __syncthreads();
}

// ---------------- prep ----------------
__global__ void k_init() {
    int i = blockIdx.x * 256 + threadIdx.x;
    if (i < BB * HH) { g_h[i] = 0.f; g_hT[i] = 0.f; g_cT[i] = 0.f; }
}

__global__ void k_prep_w(const float* __restrict__ W_ih, const float* __restrict__ b_ih,
                         const float* __restrict__ W_hh, const float* __restrict__ b_hh) {
    int idx = blockIdx.x * blockDim.x + threadIdx.x;
    if (idx >= KX * G4) return;
    int k = idx >> 11;
    int col = idx & (G4 - 1);
    int u = col >> 2;
    int g = col & 3;
    int row = g * HH + u;                      // PyTorch gate order i,f,g,o
    float v = (k < CC + EE) ? W_ih[(size_t)row * (CC + EE) + k]
                            : W_hh[(size_t)row * HH + (k - (CC + EE))];
    g_Wt[idx] = v;
    if (k == 0) g_bperm[col] = b_ih[row] + b_hh[row];
}

__global__ void k_prep_wgen(const float* __restrict__ Wgen) {
    int idx = blockIdx.x * blockDim.x + threadIdx.x;
    if (idx >= HH * NC) return;
    int k = idx / NC, n = idx - k * NC;
    g_WgenT[idx] = Wgen[(size_t)n * HH + k];
}

__global__ void k_prep_embT(const int* __restrict__ text, const float* __restrict__ emb_table) {
    int idx = blockIdx.x * blockDim.x + threadIdx.x;
    if (idx >= TT * EE * BB) return;
    int b = idx & (BB - 1);
    int e = (idx >> 6) & (EE - 1);
    int t = idx >> 14;
    int tok = text[b * TT + t];
    g_embT[idx] = emb_table[(size_t)tok * EE + e];
}

// src_featT[b][h][l] = sum_c Wi2h[h][c] * src[b][l][c]
__global__ __launch_bounds__(256) void k_srcfeat(const float* __restrict__ src,
                                                 const float* __restrict__ Wi2h) {
    __shared__ __align__(16) float Wsh[16][68];
    __shared__ __align__(16) float Ssh[16][68];
    int l0 = blockIdx.x * 64;
    int h0 = blockIdx.y * 64;
    int b  = blockIdx.z;
    int tid = threadIdx.x;
    int r  = tid >> 2;
    int kq = (tid & 3) << 2;
    int th = tid & 15;
    int tl = tid >> 4;
    float acc[4][4];
#pragma unroll
    for (int i = 0; i < 4; i++)
#pragma unroll
        for (int j = 0; j < 4; j++) acc[i][j] = 0.f;

    const float* srow = src + ((size_t)b * LL + l0 + r) * CC;
    const float* wrow = Wi2h + (size_t)(h0 + r) * CC;

    for (int k0 = 0; k0 < CC; k0 += 16) {
        float4 w4 = *(const float4*)(wrow + k0 + kq);
        float4 s4 = *(const float4*)(srow + k0 + kq);
        Wsh[kq + 0][r] = w4.x; Wsh[kq + 1][r] = w4.y; Wsh[kq + 2][r] = w4.z; Wsh[kq + 3][r] = w4.w;
        Ssh[kq + 0][r] = s4.x; Ssh[kq + 1][r] = s4.y; Ssh[kq + 2][r] = s4.z; Ssh[kq + 3][r] = s4.w;
        __syncthreads();
#pragma unroll
        for (int kk = 0; kk < 16; kk++) {
            float4 a4 = *(const float4*)&Wsh[kk][th << 2];
            float4 b4 = *(const float4*)&Ssh[kk][tl << 2];
            float av[4] = {a4.x, a4.y, a4.z, a4.w};
            float bv[4] = {b4.x, b4.y, b4.z, b4.w};
#pragma unroll
            for (int i = 0; i < 4; i++)
#pragma unroll
                for (int j = 0; j < 4; j++) acc[i][j] += av[i] * bv[j];
        }
        __syncthreads();
    }
#pragma unroll
    for (int i = 0; i < 4; i++) {
        float4 o4 = make_float4(acc[i][0], acc[i][1], acc[i][2], acc[i][3]);
        *(float4*)&g_srcfT[((size_t)b * HH + h0 + (th << 2) + i) * LL + l0 + (tl << 2)] = o4;
    }
}

// ---------------- persistent step-loop kernel ----------------
__global__ __launch_bounds__(256, 2) void k_steps(const float* __restrict__ src,
                                                  const float* __restrict__ Wh2h,
                                                  const float* __restrict__ bh2h,
                                                  const float* __restrict__ wscore) {
    __shared__ __align__(16) float sm[4096];   // 16 KB, reused per phase
    int bid = blockIdx.x;
    int tid = threadIdx.x;

    for (int t = 0; t < TT; t++) {
        // ===== phase 1: proj[b][j] = Wh2h[j][:] . h[b][:] + bh2h[j] =====
        // 256 blocks: 32 j-tiles(16) x 8 b-tiles(8); warp handles 2 j rows
        {
            float* hsh = sm;                    // 8 x 512
            int j0 = (bid & 31) << 4;
            int b0 = (bid >> 5) << 3;
            for (int i = tid; i < 8 * HH; i += 256)
                hsh[i] = __ldcg(&g_h[(b0 + (i >> 9)) * HH + (i & 511)]);
            __syncthreads();
            int w = tid >> 5, lane = tid & 31;
#pragma unroll
            for (int jj = 0; jj < 2; jj++) {
                int j = j0 + w * 2 + jj;
                float wreg[16];
                const float* wr = Wh2h + (size_t)j * HH;
#pragma unroll
                for (int i = 0; i < 16; i++) wreg[i] = wr[lane + i * 32];
                float bj = bh2h[j];
                for (int bb = 0; bb < 8; bb++) {
                    float acc = 0.f;
#pragma unroll
                    for (int i = 0; i < 16; i++) acc += wreg[i] * hsh[bb * HH + lane + i * 32];
#pragma unroll
                    for (int o = 16; o; o >>= 1) acc += __shfl_xor_sync(0xFFFFFFFFu, acc, o);
                    if (lane == 0) g_proj[(b0 + bb) * HH + j] = acc + bj;
                }
            }
        }
        gsync();

        // ===== phase 2: score partials; 256 blocks (4 h-chunks x 64 b) =====
        {
            float* psh = sm;          // 128
            float* wsh = sm + 128;    // 128
            int hc = bid >> 6, b = bid & 63;
            int h0 = hc << 7;
            if (tid < 128) {
                psh[tid] = __ldcg(&g_proj[(b << 9) + h0 + tid]);
                wsh[tid] = wscore[h0 + tid];
            }
            __syncthreads();
            const float* sf = g_srcfT + ((size_t)b * HH + h0) * LL;
            float lg0 = 0.f, lg1 = 0.f;
#pragma unroll 4
            for (int h = 0; h < 128; h++) {
                float p = psh[h], wv = wsh[h];
                lg0 += tanh_fast(sf[(size_t)h * LL + tid] + p) * wv;
                if (tid < 128)
                    lg1 += tanh_fast(sf[(size_t)h * LL + tid + 256] + p) * wv;
            }
            g_lgp[(hc * BB + b) * LL + tid] = lg0;
            if (tid < 128) g_lgp[(hc * BB + b) * LL + tid + 256] = lg1;
        }
        gsync();

        // ===== phase 3: softmax + context; 256 blocks (4 c-chunks x 64 b) =====
        {
            float* lg    = sm;          // 384
            float* alpha = sm + 384;    // 384
            float* red   = sm + 768;    // 8
            float* bcv   = sm + 776;    // 2
            float* psum  = sm + 784;    // 256
            int cc = bid >> 6, b = bid & 63;
            const float* lp = g_lgp + b * LL;
            for (int l = tid; l < LL; l += 256)
                lg[l] = __ldcg(lp + l) + __ldcg(lp + BB * LL + l)
                      + __ldcg(lp + 2 * BB * LL + l) + __ldcg(lp + 3 * BB * LL + l);
            __syncthreads();
            float m = lg[tid];
            if (tid < 128) m = fmaxf(m, lg[tid + 256]);
#pragma unroll
            for (int o = 16; o; o >>= 1) m = fmaxf(m, __shfl_xor_sync(0xFFFFFFFFu, m, o));
            if ((tid & 31) == 0) red[tid >> 5] = m;
            __syncthreads();
            if (tid == 0) {
                float mm = red[0];
#pragma unroll
                for (int i = 1; i < 8; i++) mm = fmaxf(mm, red[i]);
                bcv[0] = mm;
            }
            __syncthreads();
            float mx = bcv[0];
            float s = 0.f;
            for (int l = tid; l < LL; l += 256) {
                float e = __expf(lg[l] - mx);
                alpha[l] = e;
                s += e;
            }
#pragma unroll
            for (int o = 16; o; o >>= 1) s += __shfl_xor_sync(0xFFFFFFFFu, s, o);
            if ((tid & 31) == 0) red[tid >> 5] = s;
            __syncthreads();
            if (tid == 0) {
                float ss = 0.f;
#pragma unroll
                for (int i = 0; i < 8; i++) ss += red[i];
                bcv[1] = ss;
            }
            __syncthreads();
            float inv = __fdividef(1.f, bcv[1]);
            int c = (cc << 7) + (tid & 127);
            int lb = (tid >> 7) * 192;
            const float* sp = src + (size_t)b * LL * CC + (size_t)lb * CC + c;
            float acc = 0.f;
#pragma unroll 8
            for (int l = 0; l < 192; l++) acc += alpha[lb + l] * sp[(size_t)l * CC];
            psum[tid] = acc;
            __syncthreads();
            if (tid < 128) g_X[c * BB + b] = (psum[tid] + psum[tid + 128]) * inv;
        }
        gsync();

        // ===== phase 4: gate GEMM partials; 256 blocks (16 m-tiles x 16 k-slices) =====
        {
            float (*Wsh)[128] = (float (*)[128])sm;            // 16x128
            float (*Xsh)[64]  = (float (*)[64])(sm + 2048);    // 16x64
            int mt = bid & 15, ks = bid >> 4;
            int m0 = mt << 7;
            int k0b = ks * KSLICE;
            int tx = tid & 15;
            int ty = tid >> 4;
            int srow = tid >> 4;
            int wcol = (tid & 15) << 3;
            int xcol = (tid & 15) << 2;
            float acc[8][4];
#pragma unroll
            for (int i = 0; i < 8; i++)
#pragma unroll
                for (int j = 0; j < 4; j++) acc[i][j] = 0.f;

            for (int kc = 0; kc < KSLICE; kc += 16) {
                int k0 = k0b + kc;
                const float* wp = g_Wt + (size_t)(k0 + srow) * G4 + m0 + wcol;
                *(float4*)&Wsh[srow][wcol]     = *(const float4*)wp;
                *(float4*)&Wsh[srow][wcol + 4] = *(const float4*)(wp + 4);
                int r = k0 + srow;
                const float* xr = (r < CC) ? (g_X + r * BB)
                                : (r < CC + EE) ? (g_embT + ((size_t)t * EE + (r - CC)) * BB)
                                                : (g_hT + (r - CC - EE) * BB);
                *(float4*)&Xsh[srow][xcol] = __ldcg((const float4*)(xr + xcol));
                __syncthreads();
#pragma unroll
                for (int kk = 0; kk < 16; kk++) {
                    float4 a0 = *(const float4*)&Wsh[kk][ty << 3];
                    float4 a1 = *(const float4*)&Wsh[kk][(ty << 3) + 4];
                    float4 bx = *(const float4*)&Xsh[kk][tx << 2];
                    float av[8] = {a0.x, a0.y, a0.z, a0.w, a1.x, a1.y, a1.z, a1.w};
                    float bv[4] = {bx.x, bx.y, bx.z, bx.w};
#pragma unroll
                    for (int i = 0; i < 8; i++)
#pragma unroll
                        for (int j = 0; j < 4; j++) acc[i][j] += av[i] * bv[j];
                }
                __syncthreads();
            }
            float* op = g_gp + ((size_t)ks * G4 + m0 + (ty << 3)) * BB + (tx << 2);
#pragma unroll
            for (int i = 0; i < 8; i++)
                *(float4*)(op + (size_t)i * BB) =
                    make_float4(acc[i][0], acc[i][1], acc[i][2], acc[i][3]);
        }
        gsync();

        // ===== phase 5: cell update; 128 blocks =====
        if (bid < 128) {
            int idx = bid * 256 + tid;
            int b = idx & (BB - 1);
            int u = idx >> 6;
            float4 bias = *(const float4*)&g_bperm[u << 2];
            float a0 = bias.x, a1 = bias.y, a2 = bias.z, a3 = bias.w;
            const float* gp = g_gp + ((size_t)(u << 2)) * BB + b;
#pragma unroll
            for (int ks = 0; ks < KSPLIT; ks++) {
                const float* p = gp + (size_t)ks * G4 * BB;
                a0 += __ldcg(p);
                a1 += __ldcg(p + BB);
                a2 += __ldcg(p + 2 * BB);
                a3 += __ldcg(p + 3 * BB);
            }
            float ig = sigm(a0);
            float fg = sigm(a1);
            float gg = tanh_acc(a2);
            float og = sigm(a3);
            int uc = u * BB + b;
            float cn = fg * __ldcg(&g_cT[uc]) + ig * gg;
            float hn = og * tanh_acc(cn);
            g_cT[uc] = cn;
            g_hT[uc] = hn;
            g_h[b * HH + u] = hn;
            g_hs[((size_t)(b * TT + t)) * HH + u] = hn;
        }
        gsync();
    }
}

// final: probs[m][n] = hs[m][:] . WgenT[:][n] + bgen[n]
__global__ __launch_bounds__(256) void k_out(const float* __restrict__ bgen,
                                             float* __restrict__ out) {
    __shared__ __align__(16) float Ash[16][68];
    __shared__ __align__(16) float Bsh[16][68];
    int m0 = blockIdx.x * 64;
    int n0 = blockIdx.y * 64;
    int tid = threadIdx.x;
    int r  = tid >> 2;
    int kq = (tid & 3) << 2;
    int bkk = tid >> 4;
    int nq  = (tid & 15) << 2;
    int tm = tid & 15;
    int tn = tid >> 4;
    float acc[4][4];
#pragma unroll
    for (int i = 0; i < 4; i++)
#pragma unroll
        for (int j = 0; j < 4; j++) acc[i][j] = 0.f;

    for (int k0 = 0; k0 < HH; k0 += 16) {
        float4 a4 = *(const float4*)&g_hs[(size_t)(m0 + r) * HH + k0 + kq];
        Ash[kq + 0][r] = a4.x; Ash[kq + 1][r] = a4.y; Ash[kq + 2][r] = a4.z; Ash[kq + 3][r] = a4.w;
#pragma unroll
        for (int j = 0; j < 4; j++) {
            int n = n0 + nq + j;
            Bsh[bkk][nq + j] = (n < NC) ? g_WgenT[(size_t)(k0 + bkk) * NC + n] : 0.f;
        }
        __syncthreads();
#pragma unroll
        for (int kk = 0; kk < 16; kk++) {
            float4 av4 = *(const float4*)&Ash[kk][tm << 2];
            float4 bv4 = *(const float4*)&Bsh[kk][tn << 2];
            float av[4] = {av4.x, av4.y, av4.z, av4.w};
            float bv[4] = {bv4.x, bv4.y, bv4.z, bv4.w};
#pragma unroll
            for (int i = 0; i < 4; i++)
#pragma unroll
                for (int j = 0; j < 4; j++) acc[i][j] += av[i] * bv[j];
        }
        __syncthreads();
    }
#pragma unroll
    for (int i = 0; i < 4; i++) {
        int m = m0 + (tm << 2) + i;
#pragma unroll
        for (int j = 0; j < 4; j++) {
            int n = n0 + (tn << 2) + j;
            if (n < NC) out[(size_t)m * NC + n] = acc[i][j] + bgen[n];
        }
    }
}

// ---------------- launch ----------------
extern "C" void kernel_launch(void* const* d_in, const int* in_sizes, int n_in,
                              void* d_out, int out_size) {
    const float* src       = (const float*)d_in[0];
    const int*   text      = (const int*)d_in[1];
    const float* emb_table = (const float*)d_in[2];
    const float* Wi2h      = (const float*)d_in[3];
    const float* Wh2h      = (const float*)d_in[4];
    const float* bh2h      = (const float*)d_in[5];
    const float* wscore    = (const float*)d_in[6];
    const float* W_ih      = (const float*)d_in[7];
    const float* b_ih      = (const float*)d_in[8];
    const float* W_hh      = (const float*)d_in[9];
    const float* b_hh      = (const float*)d_in[10];
    const float* Wgen      = (const float*)d_in[11];
    const float* bgen      = (const float*)d_in[12];
    float* out = (float*)d_out;
    (void)in_sizes; (void)n_in; (void)out_size;

    k_init<<<128, 256>>>();
    k_prep_w<<<(KX * G4 + 255) / 256, 256>>>(W_ih, b_ih, W_hh, b_hh);
    k_prep_wgen<<<(HH * NC + 255) / 256, 256>>>(Wgen);
    k_prep_embT<<<(TT * EE * BB + 255) / 256, 256>>>(text, emb_table);
    k_srcfeat<<<dim3(LL / 64, HH / 64, BB), 256>>>(src, Wi2h);

    k_steps<<<NBLK, 256>>>(src, Wh2h, bh2h, wscore);

    k_out<<<dim3(127, 4), 256>>>(bgen, out);
}

// round 14
// speedup vs baseline: 1.0636x; 1.0636x over previous
#include <cuda_runtime.h>
#include <cuda_bf16.h>
#include <math.h>

#define BB 64
#define LL 384
#define CC 512
#define HH 512
#define EE 256
#define NC 250
#define TT 127
#define KX 1280     // C + E + H
#define G4 2048     // 4*H
#define KSPLIT 16
#define KSLICE 80   // KX / KSPLIT
#define NBLK 256    // persistent grid size

// ---------------- device scratch ----------------
__device__ __align__(16) float g_srcfT[(size_t)BB * HH * LL];   // [b][h][l]
__device__ __align__(16) float g_Wt[(size_t)KX * G4];           // [k][u*4+g]
__device__ __align__(16) float g_bperm[G4];
__device__ __align__(16) float g_WgenT[HH * NC];                // [k][n]
__device__ __align__(16) float g_embT[(size_t)TT * EE * BB];    // [t][e][b]
__device__ __align__(16) float g_h[BB * HH];                    // [b][u]
__device__ __align__(16) float g_hT[HH * BB];                   // [u][b]
__device__ __align__(16) float g_cT[HH * BB];                   // [u][b]
__device__ __align__(16) float g_proj[BB * HH];
__device__ __align__(16) float g_lgp[4 * BB * LL];              // score partials
__device__ __align__(16) float g_X[CC * BB];                    // context transposed [c][b]
__device__ __align__(16) float g_gp[(size_t)KSPLIT * G4 * BB];  // gate partials
__device__ __align__(16) float g_hs[(size_t)BB * TT * HH];

// tree barrier state (monotonic counters; reset by k_init each launch)
__device__ unsigned g_grp[16];
__device__ unsigned g_root;
__device__ unsigned g_gen;

// ---------------- math ----------------
__device__ __forceinline__ float tanh_fast(float x) {
    float y;
    asm("tanh.approx.f32 %0, %1;" : "=f"(y) : "f"(x));
    return y;
}
__device__ __forceinline__ float tanh_acc(float x) {
    float a = fabsf(x);
    float e = __expf(-2.0f * a);
    float r = __fdividef(1.0f - e, 1.0f + e);
    return copysignf(r, x);
}
__device__ __forceinline__ float sigm(float x) {
    return __fdividef(1.0f, 1.0f + __expf(-x));
}

// two-level tree grid barrier; `my` is the per-thread barrier count
__device__ __forceinline__ void gsync(unsigned& my) {
    __syncthreads();
    my++;
    if (threadIdx.x == 0) {
        __threadfence();
        if ((atomicAdd(&g_grp[blockIdx.x & 15], 1u) & 15u) == 15u) {
            if ((atomicAdd(&g_root, 1u) & 15u) == 15u) {
                atomicAdd(&g_gen, 1u);
            }
        }
        while (*(volatile unsigned*)&g_gen < my) { __nanosleep(64); }
        __threadfence();
    }
    __syncthreads();
}

// ---------------- prep ----------------
// fused: weight permute + WgenT + embT  (grid 10240 x 256)
__global__ void k_prep_all(const float* __restrict__ W_ih, const float* __restrict__ b_ih,
                           const float* __restrict__ W_hh, const float* __restrict__ b_hh,
                           const float* __restrict__ Wgen,
                           const int* __restrict__ text, const float* __restrict__ emb_table) {
    int idx = blockIdx.x * 256 + threadIdx.x;
    // Wt permute: [k][u*4+g]
    {
        int k = idx >> 11;
        int col = idx & (G4 - 1);
        int u = col >> 2;
        int g = col & 3;
        int row = g * HH + u;                  // PyTorch gate order i,f,g,o
        float v = (k < CC + EE) ? W_ih[(size_t)row * (CC + EE) + k]
                                : W_hh[(size_t)row * HH + (k - (CC + EE))];
        g_Wt[idx] = v;
        if (k == 0) g_bperm[col] = b_ih[row] + b_hh[row];
    }
    // embT
    if (idx < TT * EE * BB) {
        int b = idx & (BB - 1);
        int e = (idx >> 6) & (EE - 1);
        int t = idx >> 14;
        int tok = text[b * TT + t];
        g_embT[idx] = emb_table[(size_t)tok * EE + e];
    }
    // WgenT
    if (idx < HH * NC) {
        int k = idx / NC, n = idx - k * NC;
        g_WgenT[idx] = Wgen[(size_t)n * HH + k];
    }
}

// init state + barrier counters (runs every launch, before k_steps)
__global__ void k_init() {
    int i = blockIdx.x * 256 + threadIdx.x;
    if (i < BB * HH) { g_h[i] = 0.f; g_hT[i] = 0.f; g_cT[i] = 0.f; }
    if (i < 16) g_grp[i] = 0u;
    if (i == 0) { g_root = 0u; g_gen = 0u; }
}

// src_featT[b][h][l] = sum_c Wi2h[h][c] * src[b][l][c]
__global__ __launch_bounds__(256) void k_srcfeat(const float* __restrict__ src,
                                                 const float* __restrict__ Wi2h) {
    __shared__ __align__(16) float Wsh[16][68];
    __shared__ __align__(16) float Ssh[16][68];
    int l0 = blockIdx.x * 64;
    int h0 = blockIdx.y * 64;
    int b  = blockIdx.z;
    int tid = threadIdx.x;
    int r  = tid >> 2;
    int kq = (tid & 3) << 2;
    int th = tid & 15;
    int tl = tid >> 4;
    float acc[4][4];
#pragma unroll
    for (int i = 0; i < 4; i++)
#pragma unroll
        for (int j = 0; j < 4; j++) acc[i][j] = 0.f;

    const float* srow = src + ((size_t)b * LL + l0 + r) * CC;
    const float* wrow = Wi2h + (size_t)(h0 + r) * CC;

    for (int k0 = 0; k0 < CC; k0 += 16) {
        float4 w4 = *(const float4*)(wrow + k0 + kq);
        float4 s4 = *(const float4*)(srow + k0 + kq);
        Wsh[kq + 0][r] = w4.x; Wsh[kq + 1][r] = w4.y; Wsh[kq + 2][r] = w4.z; Wsh[kq + 3][r] = w4.w;
        Ssh[kq + 0][r] = s4.x; Ssh[kq + 1][r] = s4.y; Ssh[kq + 2][r] = s4.z; Ssh[kq + 3][r] = s4.w;
        __syncthreads();
#pragma unroll
        for (int kk = 0; kk < 16; kk++) {
            float4 a4 = *(const float4*)&Wsh[kk][th << 2];
            float4 b4 = *(const float4*)&Ssh[kk][tl << 2];
            float av[4] = {a4.x, a4.y, a4.z, a4.w};
            float bv[4] = {b4.x, b4.y, b4.z, b4.w};
#pragma unroll
            for (int i = 0; i < 4; i++)
#pragma unroll
                for (int j = 0; j < 4; j++) acc[i][j] += av[i] * bv[j];
        }
        __syncthreads();
    }
#pragma unroll
    for (int i = 0; i < 4; i++) {
        float4 o4 = make_float4(acc[i][0], acc[i][1], acc[i][2], acc[i][3]);
        *(float4*)&g_srcfT[((size_t)b * HH + h0 + (th << 2) + i) * LL + l0 + (tl << 2)] = o4;
    }
}

// ---------------- persistent step-loop kernel ----------------
__global__ __launch_bounds__(256, 2) void k_steps(const float* __restrict__ src,
                                                  const float* __restrict__ Wh2h,
                                                  const float* __restrict__ bh2h,
                                                  const float* __restrict__ wscore) {
    __shared__ __align__(16) float sm[4096];   // 16 KB, reused per phase
    int bid = blockIdx.x;
    int tid = threadIdx.x;
    unsigned my = 0;

    for (int t = 0; t < TT; t++) {
        // ===== phase 1: proj[b][j] = Wh2h[j][:] . h[b][:] + bh2h[j] =====
        // 256 blocks: 32 j-tiles(16) x 8 b-tiles(8); warp handles 2 j rows
        {
            float* hsh = sm;                    // 8 x 512
            int j0 = (bid & 31) << 4;
            int b0 = (bid >> 5) << 3;
            for (int i = tid; i < 8 * HH; i += 256)
                hsh[i] = __ldcg(&g_h[(b0 + (i >> 9)) * HH + (i & 511)]);
            __syncthreads();
            int w = tid >> 5, lane = tid & 31;
#pragma unroll
            for (int jj = 0; jj < 2; jj++) {
                int j = j0 + w * 2 + jj;
                float wreg[16];
                const float* wr = Wh2h + (size_t)j * HH;
#pragma unroll
                for (int i = 0; i < 16; i++) wreg[i] = wr[lane + i * 32];
                float bj = bh2h[j];
                for (int bb = 0; bb < 8; bb++) {
                    float acc = 0.f;
#pragma unroll
                    for (int i = 0; i < 16; i++) acc += wreg[i] * hsh[bb * HH + lane + i * 32];
#pragma unroll
                    for (int o = 16; o; o >>= 1) acc += __shfl_xor_sync(0xFFFFFFFFu, acc, o);
                    if (lane == 0) g_proj[(b0 + bb) * HH + j] = acc + bj;
                }
            }
        }
        gsync(my);

        // ===== phase 2: score partials; 256 blocks (4 h-chunks x 64 b) =====
        // balanced: every thread does 128 (pass A) + 64 (pass B) h-iters
        {
            float* psh = sm;          // 128
            float* wsh = sm + 128;    // 128
            int hc = bid >> 6, b = bid & 63;
            int h0 = hc << 7;
            if (tid < 128) {
                psh[tid] = __ldcg(&g_proj[(b << 9) + h0 + tid]);
                wsh[tid] = wscore[h0 + tid];
            }
            __syncthreads();
            const float* sf = g_srcfT + ((size_t)b * HH + h0) * LL;
            // pass A: l = tid (0..255), full 128 h
            float lgA = 0.f;
#pragma unroll 4
            for (int h = 0; h < 128; h++)
                lgA += tanh_fast(sf[(size_t)h * LL + tid] + psh[h]) * wsh[h];
            // pass B: l = 256 + (tid>>1), half h-range per thread, pair-combined
            int lB = 256 + (tid >> 1);
            int hb = (tid & 1) << 6;
            float lgB = 0.f;
#pragma unroll 4
            for (int i = 0; i < 64; i++) {
                int h = hb + i;
                lgB += tanh_fast(sf[(size_t)h * LL + lB] + psh[h]) * wsh[h];
            }
            lgB += __shfl_xor_sync(0xFFFFFFFFu, lgB, 1);
            float* lp = g_lgp + (hc * BB + b) * LL;
            lp[tid] = lgA;
            if ((tid & 1) == 0) lp[lB] = lgB;
        }
        gsync(my);

        // ===== phase 3: softmax + context; 256 blocks (4 c-chunks x 64 b) =====
        {
            float* lg    = sm;          // 384
            float* alpha = sm + 384;    // 384
            float* red   = sm + 768;    // 8
            float* bcv   = sm + 776;    // 2
            float* psum  = sm + 784;    // 256
            int cc = bid >> 6, b = bid & 63;
            const float* lp = g_lgp + b * LL;
            for (int l = tid; l < LL; l += 256)
                lg[l] = __ldcg(lp + l) + __ldcg(lp + BB * LL + l)
                      + __ldcg(lp + 2 * BB * LL + l) + __ldcg(lp + 3 * BB * LL + l);
            __syncthreads();
            float m = lg[tid];
            if (tid < 128) m = fmaxf(m, lg[tid + 256]);
#pragma unroll
            for (int o = 16; o; o >>= 1) m = fmaxf(m, __shfl_xor_sync(0xFFFFFFFFu, m, o));
            if ((tid & 31) == 0) red[tid >> 5] = m;
            __syncthreads();
            if (tid == 0) {
                float mm = red[0];
#pragma unroll
                for (int i = 1; i < 8; i++) mm = fmaxf(mm, red[i]);
                bcv[0] = mm;
            }
            __syncthreads();
            float mx = bcv[0];
            float s = 0.f;
            for (int l = tid; l < LL; l += 256) {
                float e = __expf(lg[l] - mx);
                alpha[l] = e;
                s += e;
            }
#pragma unroll
            for (int o = 16; o; o >>= 1) s += __shfl_xor_sync(0xFFFFFFFFu, s, o);
            if ((tid & 31) == 0) red[tid >> 5] = s;
            __syncthreads();
            if (tid == 0) {
                float ss = 0.f;
#pragma unroll
                for (int i = 0; i < 8; i++) ss += red[i];
                bcv[1] = ss;
            }
            __syncthreads();
            float inv = __fdividef(1.f, bcv[1]);
            int c = (cc << 7) + (tid & 127);
            int lb = (tid >> 7) * 192;
            const float* sp = src + (size_t)b * LL * CC + (size_t)lb * CC + c;
            float acc = 0.f;
#pragma unroll 8
            for (int l = 0; l < 192; l++) acc += alpha[lb + l] * sp[(size_t)l * CC];
            psum[tid] = acc;
            __syncthreads();
            if (tid < 128) g_X[c * BB + b] = (psum[tid] + psum[tid + 128]) * inv;
        }
        gsync(my);

        // ===== phase 4: gate GEMM partials; 256 blocks (16 m-tiles x 16 k-slices) =====
        {
            float (*Wsh)[128] = (float (*)[128])sm;            // 16x128
            float (*Xsh)[64]  = (float (*)[64])(sm + 2048);    // 16x64
            int mt = bid & 15, ks = bid >> 4;
            int m0 = mt << 7;
            int k0b = ks * KSLICE;
            int tx = tid & 15;
            int ty = tid >> 4;
            int srow = tid >> 4;
            int wcol = (tid & 15) << 3;
            int xcol = (tid & 15) << 2;
            float acc[8][4];
#pragma unroll
            for (int i = 0; i < 8; i++)
#pragma unroll
                for (int j = 0; j < 4; j++) acc[i][j] = 0.f;

            for (int kc = 0; kc < KSLICE; kc += 16) {
                int k0 = k0b + kc;
                const float* wp = g_Wt + (size_t)(k0 + srow) * G4 + m0 + wcol;
                *(float4*)&Wsh[srow][wcol]     = *(const float4*)wp;
                *(float4*)&Wsh[srow][wcol + 4] = *(const float4*)(wp + 4);
                int r = k0 + srow;
                const float* xr = (r < CC) ? (g_X + r * BB)
                                : (r < CC + EE) ? (g_embT + ((size_t)t * EE + (r - CC)) * BB)
                                                : (g_hT + (r - CC - EE) * BB);
                *(float4*)&Xsh[srow][xcol] = __ldcg((const float4*)(xr + xcol));
                __syncthreads();
#pragma unroll
                for (int kk = 0; kk < 16; kk++) {
                    float4 a0 = *(const float4*)&Wsh[kk][ty << 3];
                    float4 a1 = *(const float4*)&Wsh[kk][(ty << 3) + 4];
                    float4 bx = *(const float4*)&Xsh[kk][tx << 2];
                    float av[8] = {a0.x, a0.y, a0.z, a0.w, a1.x, a1.y, a1.z, a1.w};
                    float bv[4] = {bx.x, bx.y, bx.z, bx.w};
#pragma unroll
                    for (int i = 0; i < 8; i++)
#pragma unroll
                        for (int j = 0; j < 4; j++) acc[i][j] += av[i] * bv[j];
                }
                __syncthreads();
            }
            float* op = g_gp + ((size_t)ks * G4 + m0 + (ty << 3)) * BB + (tx << 2);
#pragma unroll
            for (int i = 0; i < 8; i++)
                *(float4*)(op + (size_t)i * BB) =
                    make_float4(acc[i][0], acc[i][1], acc[i][2], acc[i][3]);
        }
        gsync(my);

        // ===== phase 5: cell update; all 256 blocks, partial-sum split across halves =====
        {
            float4* cpart = (float4*)sm;
            int o = tid & 127;
            int half = tid >> 7;
            int idx = bid * 128 + o;              // 0..32767
            int b = idx & (BB - 1);
            int u = idx >> 6;
            const float* gp = g_gp + ((size_t)(u << 2)) * BB + b;
            float a0 = 0.f, a1 = 0.f, a2 = 0.f, a3 = 0.f;
#pragma unroll
            for (int ks = 0; ks < 8; ks++) {
                const float* p = gp + (size_t)(half * 8 + ks) * G4 * BB;
                a0 += __ldcg(p);
                a1 += __ldcg(p + BB);
                a2 += __ldcg(p + 2 * BB);
                a3 += __ldcg(p + 3 * BB);
            }
            cpart[tid] = make_float4(a0, a1, a2, a3);
            __syncthreads();
            if (half == 0) {
                float4 q = cpart[tid + 128];
                float4 bias = *(const float4*)&g_bperm[u << 2];
                a0 += q.x + bias.x;
                a1 += q.y + bias.y;
                a2 += q.z + bias.z;
                a3 += q.w + bias.w;
                float ig = sigm(a0);
                float fg = sigm(a1);
                float gg = tanh_acc(a2);
                float og = sigm(a3);
                int uc = u * BB + b;
                float cn = fg * __ldcg(&g_cT[uc]) + ig * gg;
                float hn = og * tanh_acc(cn);
                g_cT[uc] = cn;
                g_hT[uc] = hn;
                g_h[b * HH + u] = hn;
                g_hs[((size_t)(b * TT + t)) * HH + u] = hn;
            }
        }
        gsync(my);
    }
}

// final: probs[m][n] = hs[m][:] . WgenT[:][n] + bgen[n]
__global__ __launch_bounds__(256) void k_out(const float* __restrict__ bgen,
                                             float* __restrict__ out) {
    __shared__ __align__(16) float Ash[16][68];
    __shared__ __align__(16) float Bsh[16][68];
    int m0 = blockIdx.x * 64;
    int n0 = blockIdx.y * 64;
    int tid = threadIdx.x;
    int r  = tid >> 2;
    int kq = (tid & 3) << 2;
    int bkk = tid >> 4;
    int nq  = (tid & 15) << 2;
    int tm = tid & 15;
    int tn = tid >> 4;
    float acc[4][4];
#pragma unroll
    for (int i = 0; i < 4; i++)
#pragma unroll
        for (int j = 0; j < 4; j++) acc[i][j] = 0.f;

    for (int k0 = 0; k0 < HH; k0 += 16) {
        float4 a4 = *(const float4*)&g_hs[(size_t)(m0 + r) * HH + k0 + kq];
        Ash[kq + 0][r] = a4.x; Ash[kq + 1][r] = a4.y; Ash[kq + 2][r] = a4.z; Ash[kq + 3][r] = a4.w;
#pragma unroll
        for (int j = 0; j < 4; j++) {
            int n = n0 + nq + j;
            Bsh[bkk][nq + j] = (n < NC) ? g_WgenT[(size_t)(k0 + bkk) * NC + n] : 0.f;
        }
        __syncthreads();
#pragma unroll
        for (int kk = 0; kk < 16; kk++) {
            float4 av4 = *(const float4*)&Ash[kk][tm << 2];
            float4 bv4 = *(const float4*)&Bsh[kk][tn << 2];
            float av[4] = {av4.x, av4.y, av4.z, av4.w};
            float bv[4] = {bv4.x, bv4.y, bv4.z, bv4.w};
#pragma unroll
            for (int i = 0; i < 4; i++)
#pragma unroll
                for (int j = 0; j < 4; j++) acc[i][j] += av[i] * bv[j];
        }
        __syncthreads();
    }
#pragma unroll
    for (int i = 0; i < 4; i++) {
        int m = m0 + (tm << 2) + i;
#pragma unroll
        for (int j = 0; j < 4; j++) {
            int n = n0 + (tn << 2) + j;
            if (n < NC) out[(size_t)m * NC + n] = acc[i][j] + bgen[n];
        }
    }
}

// ---------------- launch ----------------
extern "C" void kernel_launch(void* const* d_in, const int* in_sizes, int n_in,
                              void* d_out, int out_size) {
    const float* src       = (const float*)d_in[0];
    const int*   text      = (const int*)d_in[1];
    const float* emb_table = (const float*)d_in[2];
    const float* Wi2h      = (const float*)d_in[3];
    const float* Wh2h      = (const float*)d_in[4];
    const float* bh2h      = (const float*)d_in[5];
    const float* wscore    = (const float*)d_in[6];
    const float* W_ih      = (const float*)d_in[7];
    const float* b_ih      = (const float*)d_in[8];
    const float* W_hh      = (const float*)d_in[9];
    const float* b_hh      = (const float*)d_in[10];
    const float* Wgen      = (const float*)d_in[11];
    const float* bgen      = (const float*)d_in[12];
    float* out = (float*)d_out;
    (void)in_sizes; (void)n_in; (void)out_size;

    // order chosen so the ncu capture slot (my launch #3) lands on k_steps
    k_prep_all<<<KX * G4 / 256, 256>>>(W_ih, b_ih, W_hh, b_hh, Wgen, text, emb_table);
    k_srcfeat<<<dim3(LL / 64, HH / 64, BB), 256>>>(src, Wi2h);
    k_init<<<128, 256>>>();
    k_steps<<<NBLK, 256>>>(src, Wh2h, bh2h, wscore);
    k_out<<<dim3(127, 4), 256>>>(bgen, out);
}

// round 16
// speedup vs baseline: 1.5509x; 1.4582x over previous
#include <cuda_runtime.h>
#include <cuda_bf16.h>
#include <math.h>

#define BB 64
#define LL 384
#define CC 512
#define HH 512
#define EE 256
#define NC 250
#define TT 127
#define KX 1280     // C + E + H
#define G4 2048     // 4*H
#define KSPLIT 16
#define KSLICE 80   // KX / KSPLIT
#define NBLK 512    // persistent grid size (148 SMs x 4 = 592 capacity)

// ---------------- device scratch ----------------
__device__ __align__(16) float g_srcfT[(size_t)BB * HH * LL];   // [b][h][l]
__device__ __align__(16) float g_Wt[(size_t)KX * G4];           // [k][u*4+g]
__device__ __align__(16) float g_bperm[G4];
__device__ __align__(16) float g_WgenT[HH * NC];                // [k][n]
__device__ __align__(16) float g_embT[(size_t)TT * EE * BB];    // [t][e][b]
__device__ __align__(16) float g_h[BB * HH];                    // [b][u]
__device__ __align__(16) float g_hT[HH * BB];                   // [u][b]
__device__ __align__(16) float g_cT[HH * BB];                   // [u][b]
__device__ __align__(16) float g_proj[BB * HH];
__device__ __align__(16) float g_lgp[8 * BB * LL];              // score partials (8 h-chunks)
__device__ __align__(16) float g_X[CC * BB];                    // context transposed [c][b]
__device__ __align__(16) float g_gp[(size_t)KSPLIT * G4 * BB];  // gate partials
__device__ __align__(16) float g_hs[(size_t)BB * TT * HH];

// tree barrier state (monotonic counters; reset by k_init each launch)
__device__ unsigned g_grp[32];
__device__ unsigned g_root;
__device__ unsigned g_gen;

// ---------------- math ----------------
__device__ __forceinline__ float tanh_fast(float x) {
    float y;
    asm("tanh.approx.f32 %0, %1;" : "=f"(y) : "f"(x));
    return y;
}
__device__ __forceinline__ float tanh_acc(float x) {
    float a = fabsf(x);
    float e = __expf(-2.0f * a);
    float r = __fdividef(1.0f - e, 1.0f + e);
    return copysignf(r, x);
}
__device__ __forceinline__ float sigm(float x) {
    return __fdividef(1.0f, 1.0f + __expf(-x));
}

// two-level tree grid barrier: 32 groups of 16 CTAs, root counts 32 groups
__device__ __forceinline__ void gsync(unsigned& my) {
    __syncthreads();
    my++;
    if (threadIdx.x == 0) {
        __threadfence();
        if ((atomicAdd(&g_grp[blockIdx.x & 31], 1u) & 15u) == 15u) {
            if ((atomicAdd(&g_root, 1u) & 31u) == 31u) {
                atomicAdd(&g_gen, 1u);
            }
        }
        while (*(volatile unsigned*)&g_gen < my) { __nanosleep(32); }
        __threadfence();
    }
    __syncthreads();
}

// ---------------- prep ----------------
// fused: weight permute + WgenT + embT  (grid 10240 x 256)
__global__ void k_prep_all(const float* __restrict__ W_ih, const float* __restrict__ b_ih,
                           const float* __restrict__ W_hh, const float* __restrict__ b_hh,
                           const float* __restrict__ Wgen,
                           const int* __restrict__ text, const float* __restrict__ emb_table) {
    int idx = blockIdx.x * 256 + threadIdx.x;
    // Wt permute: [k][u*4+g]
    {
        int k = idx >> 11;
        int col = idx & (G4 - 1);
        int u = col >> 2;
        int g = col & 3;
        int row = g * HH + u;                  // PyTorch gate order i,f,g,o
        float v = (k < CC + EE) ? W_ih[(size_t)row * (CC + EE) + k]
                                : W_hh[(size_t)row * HH + (k - (CC + EE))];
        g_Wt[idx] = v;
        if (k == 0) g_bperm[col] = b_ih[row] + b_hh[row];
    }
    // embT
    if (idx < TT * EE * BB) {
        int b = idx & (BB - 1);
        int e = (idx >> 6) & (EE - 1);
        int t = idx >> 14;
        int tok = text[b * TT + t];
        g_embT[idx] = emb_table[(size_t)tok * EE + e];
    }
    // WgenT
    if (idx < HH * NC) {
        int k = idx / NC, n = idx - k * NC;
        g_WgenT[idx] = Wgen[(size_t)n * HH + k];
    }
}

// init state + barrier counters (runs every launch, before k_steps)
__global__ void k_init() {
    int i = blockIdx.x * 256 + threadIdx.x;
    if (i < BB * HH) { g_h[i] = 0.f; g_hT[i] = 0.f; g_cT[i] = 0.f; }
    if (i < 32) g_grp[i] = 0u;
    if (i == 0) { g_root = 0u; g_gen = 0u; }
}

// src_featT[b][h][l] = sum_c Wi2h[h][c] * src[b][l][c]
__global__ __launch_bounds__(256) void k_srcfeat(const float* __restrict__ src,
                                                 const float* __restrict__ Wi2h) {
    __shared__ __align__(16) float Wsh[16][68];
    __shared__ __align__(16) float Ssh[16][68];
    int l0 = blockIdx.x * 64;
    int h0 = blockIdx.y * 64;
    int b  = blockIdx.z;
    int tid = threadIdx.x;
    int r  = tid >> 2;
    int kq = (tid & 3) << 2;
    int th = tid & 15;
    int tl = tid >> 4;
    float acc[4][4];
#pragma unroll
    for (int i = 0; i < 4; i++)
#pragma unroll
        for (int j = 0; j < 4; j++) acc[i][j] = 0.f;

    const float* srow = src + ((size_t)b * LL + l0 + r) * CC;
    const float* wrow = Wi2h + (size_t)(h0 + r) * CC;

    for (int k0 = 0; k0 < CC; k0 += 16) {
        float4 w4 = *(const float4*)(wrow + k0 + kq);
        float4 s4 = *(const float4*)(srow + k0 + kq);
        Wsh[kq + 0][r] = w4.x; Wsh[kq + 1][r] = w4.y; Wsh[kq + 2][r] = w4.z; Wsh[kq + 3][r] = w4.w;
        Ssh[kq + 0][r] = s4.x; Ssh[kq + 1][r] = s4.y; Ssh[kq + 2][r] = s4.z; Ssh[kq + 3][r] = s4.w;
        __syncthreads();
#pragma unroll
        for (int kk = 0; kk < 16; kk++) {
            float4 a4 = *(const float4*)&Wsh[kk][th << 2];
            float4 b4 = *(const float4*)&Ssh[kk][tl << 2];
            float av[4] = {a4.x, a4.y, a4.z, a4.w};
            float bv[4] = {b4.x, b4.y, b4.z, b4.w};
#pragma unroll
            for (int i = 0; i < 4; i++)
#pragma unroll
                for (int j = 0; j < 4; j++) acc[i][j] += av[i] * bv[j];
        }
        __syncthreads();
    }
#pragma unroll
    for (int i = 0; i < 4; i++) {
        float4 o4 = make_float4(acc[i][0], acc[i][1], acc[i][2], acc[i][3]);
        *(float4*)&g_srcfT[((size_t)b * HH + h0 + (th << 2) + i) * LL + l0 + (tl << 2)] = o4;
    }
}

// ---------------- persistent step-loop kernel (512 CTAs, 4/SM) ----------------
__global__ __launch_bounds__(256, 4) void k_steps(const float* __restrict__ src,
                                                  const float* __restrict__ Wh2h,
                                                  const float* __restrict__ bh2h,
                                                  const float* __restrict__ wscore) {
    __shared__ __align__(16) float sm[4096];   // 16 KB, reused per phase
    int bid = blockIdx.x;
    int tid = threadIdx.x;
    unsigned my = 0;

    for (int t = 0; t < TT; t++) {
        // ===== phase 1: proj[b][j] = Wh2h[j][:] . h[b][:] + bh2h[j] =====
        // 512 blocks: 32 j-tiles(16) x 16 b-tiles(4); warp handles 2 j rows
        {
            float* hsh = sm;                    // 4 x 512
            int j0 = (bid & 31) << 4;
            int b0 = (bid >> 5) << 2;
            for (int i = tid; i < 4 * HH; i += 256)
                hsh[i] = __ldcg(&g_h[(b0 + (i >> 9)) * HH + (i & 511)]);
            __syncthreads();
            int w = tid >> 5, lane = tid & 31;
#pragma unroll
            for (int jj = 0; jj < 2; jj++) {
                int j = j0 + w * 2 + jj;
                float wreg[16];
                const float* wr = Wh2h + (size_t)j * HH;
#pragma unroll
                for (int i = 0; i < 16; i++) wreg[i] = wr[lane + i * 32];
                float bj = bh2h[j];
#pragma unroll
                for (int bb = 0; bb < 4; bb++) {
                    float acc = 0.f;
#pragma unroll
                    for (int i = 0; i < 16; i++) acc += wreg[i] * hsh[bb * HH + lane + i * 32];
#pragma unroll
                    for (int o = 16; o; o >>= 1) acc += __shfl_xor_sync(0xFFFFFFFFu, acc, o);
                    if (lane == 0) g_proj[(b0 + bb) * HH + j] = acc + bj;
                }
            }
        }
        gsync(my);

        // ===== phase 2: score partials; 512 blocks (8 h-chunks(64) x 64 b) =====
        {
            float* psh = sm;          // 64
            float* wsh = sm + 64;     // 64
            int hc = bid >> 6, b = bid & 63;
            int h0 = hc << 6;
            if (tid < 64) {
                psh[tid] = __ldcg(&g_proj[(b << 9) + h0 + tid]);
                wsh[tid] = wscore[h0 + tid];
            }
            __syncthreads();
            const float* sf = g_srcfT + ((size_t)b * HH + h0) * LL;
            // pass A: l = tid (0..255), all 64 h
            float lgA = 0.f;
#pragma unroll 8
            for (int h = 0; h < 64; h++)
                lgA += tanh_fast(__ldcg(&sf[(size_t)h * LL + tid]) + psh[h]) * wsh[h];
            // pass B: l = 256 + (tid>>1), half h-range per thread, pair-combined
            int lB = 256 + (tid >> 1);
            int hb = (tid & 1) << 5;
            float lgB = 0.f;
#pragma unroll 8
            for (int i = 0; i < 32; i++) {
                int h = hb + i;
                lgB += tanh_fast(__ldcg(&sf[(size_t)h * LL + lB]) + psh[h]) * wsh[h];
            }
            lgB += __shfl_xor_sync(0xFFFFFFFFu, lgB, 1);
            float* lp = g_lgp + (hc * BB + b) * LL;
            lp[tid] = lgA;
            if ((tid & 1) == 0) lp[lB] = lgB;
        }
        gsync(my);

        // ===== phase 3: softmax + context; 512 blocks (8 c-chunks(64) x 64 b) =====
        {
            float* lg    = sm;          // 384
            float* alpha = sm + 384;    // 384
            float* red   = sm + 768;    // 8
            float* bcv   = sm + 776;    // 2
            float* psum  = sm + 784;    // 256
            int cc = bid >> 6, b = bid & 63;
            const float* lp = g_lgp + b * LL;
            for (int l = tid; l < LL; l += 256) {
                float v = 0.f;
#pragma unroll
                for (int p = 0; p < 8; p++) v += __ldcg(lp + p * BB * LL + l);
                lg[l] = v;
            }
            __syncthreads();
            float m = lg[tid];
            if (tid < 128) m = fmaxf(m, lg[tid + 256]);
#pragma unroll
            for (int o = 16; o; o >>= 1) m = fmaxf(m, __shfl_xor_sync(0xFFFFFFFFu, m, o));
            if ((tid & 31) == 0) red[tid >> 5] = m;
            __syncthreads();
            if (tid == 0) {
                float mm = red[0];
#pragma unroll
                for (int i = 1; i < 8; i++) mm = fmaxf(mm, red[i]);
                bcv[0] = mm;
            }
            __syncthreads();
            float mx = bcv[0];
            float s = 0.f;
            for (int l = tid; l < LL; l += 256) {
                float e = __expf(lg[l] - mx);
                alpha[l] = e;
                s += e;
            }
#pragma unroll
            for (int o = 16; o; o >>= 1) s += __shfl_xor_sync(0xFFFFFFFFu, s, o);
            if ((tid & 31) == 0) red[tid >> 5] = s;
            __syncthreads();
            if (tid == 0) {
                float ss = 0.f;
#pragma unroll
                for (int i = 0; i < 8; i++) ss += red[i];
                bcv[1] = ss;
            }
            __syncthreads();
            float inv = __fdividef(1.f, bcv[1]);
            // context: 64 c's, 4-way l-split (96 l per thread)
            int c = (cc << 6) + (tid & 63);
            int lb = (tid >> 6) * 96;
            const float* sp = src + (size_t)b * LL * CC + (size_t)lb * CC + c;
            float acc = 0.f;
#pragma unroll 8
            for (int l = 0; l < 96; l++) acc += alpha[lb + l] * __ldcg(&sp[(size_t)l * CC]);
            psum[tid] = acc;
            __syncthreads();
            if (tid < 64)
                g_X[c * BB + b] = (psum[tid] + psum[tid + 64] + psum[tid + 128] + psum[tid + 192]) * inv;
        }
        gsync(my);

        // ===== phase 4: gate GEMM partials; 512 blocks (32 m-tiles(64) x 16 k-slices) =====
        {
            float (*Wsh)[64] = (float (*)[64])sm;              // 16x64
            float (*Xsh)[64] = (float (*)[64])(sm + 1024);     // 16x64
            int mt = bid & 31, ks = bid >> 5;
            int m0 = mt << 6;
            int k0b = ks * KSLICE;
            int tx = tid & 15;
            int ty = tid >> 4;
            int srow = tid >> 4;
            int scol = (tid & 15) << 2;
            float acc[4][4];
#pragma unroll
            for (int i = 0; i < 4; i++)
#pragma unroll
                for (int j = 0; j < 4; j++) acc[i][j] = 0.f;

            for (int kc = 0; kc < KSLICE; kc += 16) {
                int k0 = k0b + kc;
                *(float4*)&Wsh[srow][scol] =
                    *(const float4*)(g_Wt + (size_t)(k0 + srow) * G4 + m0 + scol);
                int r = k0 + srow;
                const float* xr = (r < CC) ? (g_X + r * BB)
                                : (r < CC + EE) ? (g_embT + ((size_t)t * EE + (r - CC)) * BB)
                                                : (g_hT + (r - CC - EE) * BB);
                *(float4*)&Xsh[srow][scol] = __ldcg((const float4*)(xr + scol));
                __syncthreads();
#pragma unroll
                for (int kk = 0; kk < 16; kk++) {
                    float4 a4 = *(const float4*)&Wsh[kk][ty << 2];
                    float4 b4 = *(const float4*)&Xsh[kk][tx << 2];
                    float av[4] = {a4.x, a4.y, a4.z, a4.w};
                    float bv[4] = {b4.x, b4.y, b4.z, b4.w};
#pragma unroll
                    for (int i = 0; i < 4; i++)
#pragma unroll
                        for (int j = 0; j < 4; j++) acc[i][j] += av[i] * bv[j];
                }
                __syncthreads();
            }
            float* op = g_gp + ((size_t)ks * G4 + m0 + (ty << 2)) * BB + (tx << 2);
#pragma unroll
            for (int i = 0; i < 4; i++)
                *(float4*)(op + (size_t)i * BB) =
                    make_float4(acc[i][0], acc[i][1], acc[i][2], acc[i][3]);
        }
        gsync(my);

        // ===== phase 5: cell update; 512 blocks x 64 (u,b), 4-way partial split =====
        {
            float4* cpart = (float4*)sm;          // 256 float4
            int o = tid & 63;
            int part = tid >> 6;                  // 0..3
            int idx = bid * 64 + o;               // 0..32767
            int b = idx & (BB - 1);
            int u = idx >> 6;
            const float* gp = g_gp + ((size_t)(u << 2)) * BB + b;
            float a0 = 0.f, a1 = 0.f, a2 = 0.f, a3 = 0.f;
#pragma unroll
            for (int ks = 0; ks < 4; ks++) {
                const float* p = gp + (size_t)(part * 4 + ks) * G4 * BB;
                a0 += __ldcg(p);
                a1 += __ldcg(p + BB);
                a2 += __ldcg(p + 2 * BB);
                a3 += __ldcg(p + 3 * BB);
            }
            cpart[tid] = make_float4(a0, a1, a2, a3);
            __syncthreads();
            if (part == 0) {
                float4 q1 = cpart[tid + 64];
                float4 q2 = cpart[tid + 128];
                float4 q3 = cpart[tid + 192];
                float4 bias = *(const float4*)&g_bperm[u << 2];
                a0 += q1.x + q2.x + q3.x + bias.x;
                a1 += q1.y + q2.y + q3.y + bias.y;
                a2 += q1.z + q2.z + q3.z + bias.z;
                a3 += q1.w + q2.w + q3.w + bias.w;
                float ig = sigm(a0);
                float fg = sigm(a1);
                float gg = tanh_acc(a2);
                float og = sigm(a3);
                int uc = u * BB + b;
                float cn = fg * __ldcg(&g_cT[uc]) + ig * gg;
                float hn = og * tanh_acc(cn);
                g_cT[uc] = cn;
                g_hT[uc] = hn;
                g_h[b * HH + u] = hn;
                __stcs(&g_hs[((size_t)(b * TT + t)) * HH + u], hn);
            }
        }
        gsync(my);
    }
}

// final: probs[m][n] = hs[m][:] . WgenT[:][n] + bgen[n]
__global__ __launch_bounds__(256) void k_out(const float* __restrict__ bgen,
                                             float* __restrict__ out) {
    __shared__ __align__(16) float Ash[16][68];
    __shared__ __align__(16) float Bsh[16][68];
    int m0 = blockIdx.x * 64;
    int n0 = blockIdx.y * 64;
    int tid = threadIdx.x;
    int r  = tid >> 2;
    int kq = (tid & 3) << 2;
    int bkk = tid >> 4;
    int nq  = (tid & 15) << 2;
    int tm = tid & 15;
    int tn = tid >> 4;
    float acc[4][4];
#pragma unroll
    for (int i = 0; i < 4; i++)
#pragma unroll
        for (int j = 0; j < 4; j++) acc[i][j] = 0.f;

    for (int k0 = 0; k0 < HH; k0 += 16) {
        float4 a4 = *(const float4*)&g_hs[(size_t)(m0 + r) * HH + k0 + kq];
        Ash[kq + 0][r] = a4.x; Ash[kq + 1][r] = a4.y; Ash[kq + 2][r] = a4.z; Ash[kq + 3][r] = a4.w;
#pragma unroll
        for (int j = 0; j < 4; j++) {
            int n = n0 + nq + j;
            Bsh[bkk][nq + j] = (n < NC) ? g_WgenT[(size_t)(k0 + bkk) * NC + n] : 0.f;
        }
        __syncthreads();
#pragma unroll
        for (int kk = 0; kk < 16; kk++) {
            float4 av4 = *(const float4*)&Ash[kk][tm << 2];
            float4 bv4 = *(const float4*)&Bsh[kk][tn << 2];
            float av[4] = {av4.x, av4.y, av4.z, av4.w};
            float bv[4] = {bv4.x, bv4.y, bv4.z, bv4.w};
#pragma unroll
            for (int i = 0; i < 4; i++)
#pragma unroll
                for (int j = 0; j < 4; j++) acc[i][j] += av[i] * bv[j];
        }
        __syncthreads();
    }
#pragma unroll
    for (int i = 0; i < 4; i++) {
        int m = m0 + (tm << 2) + i;
#pragma unroll
        for (int j = 0; j < 4; j++) {
            int n = n0 + (tn << 2) + j;
            if (n < NC) out[(size_t)m * NC + n] = acc[i][j] + bgen[n];
        }
    }
}

// ---------------- launch ----------------
extern "C" void kernel_launch(void* const* d_in, const int* in_sizes, int n_in,
                              void* d_out, int out_size) {
    const float* src       = (const float*)d_in[0];
    const int*   text      = (const int*)d_in[1];
    const float* emb_table = (const float*)d_in[2];
    const float* Wi2h      = (const float*)d_in[3];
    const float* Wh2h      = (const float*)d_in[4];
    const float* bh2h      = (const float*)d_in[5];
    const float* wscore    = (const float*)d_in[6];
    const float* W_ih      = (const float*)d_in[7];
    const float* b_ih      = (const float*)d_in[8];
    const float* W_hh      = (const float*)d_in[9];
    const float* b_hh      = (const float*)d_in[10];
    const float* Wgen      = (const float*)d_in[11];
    const float* bgen      = (const float*)d_in[12];
    float* out = (float*)d_out;
    (void)in_sizes; (void)n_in; (void)out_size;

    // order chosen so the ncu capture slot lands on k_steps
    k_prep_all<<<KX * G4 / 256, 256>>>(W_ih, b_ih, W_hh, b_hh, Wgen, text, emb_table);
    k_srcfeat<<<dim3(LL / 64, HH / 64, BB), 256>>>(src, Wi2h);
    k_init<<<128, 256>>>();
    k_steps<<<NBLK, 256>>>(src, Wh2h, bh2h, wscore);
    k_out<<<dim3(127, 4), 256>>>(bgen, out);
}

// round 17
// speedup vs baseline: 1.7159x; 1.1064x over previous
#include <cuda_runtime.h>
#include <cuda_bf16.h>
#include <math.h>

#define BB 64
#define LL 384
#define CC 512
#define HH 512
#define EE 256
#define NC 250
#define TT 127
#define KX 1280     // C + E + H
#define G4 2048     // 4*H
#define KSPLIT 16
#define KSLICE 80   // KX / KSPLIT
#define NBLK 512    // persistent grid size (148 SMs x 4 = 592 capacity)

// ---------------- device scratch ----------------
__device__ __align__(16) __nv_bfloat16 g_srcfT[(size_t)BB * HH * LL];  // [b][h][l] bf16
__device__ __align__(16) float g_Wt[(size_t)KX * G4];           // [k][u*4+g]
__device__ __align__(16) float g_bperm[G4];
__device__ __align__(16) float g_WgenT[HH * NC];                // [k][n]
__device__ __align__(16) float g_embT[(size_t)TT * EE * BB];    // [t][e][b]
__device__ __align__(16) float g_h[BB * HH];                    // [b][u]
__device__ __align__(16) float g_hT[HH * BB];                   // [u][b]
__device__ __align__(16) float g_cT[HH * BB];                   // [u][b]
__device__ __align__(16) float g_proj[BB * HH];
__device__ __align__(16) float g_lgp[8 * BB * LL];              // score partials (8 h-chunks)
__device__ __align__(16) float g_X[CC * BB];                    // context transposed [c][b]
__device__ __align__(16) float g_gp[(size_t)KSPLIT * G4 * BB];  // gate partials
__device__ __align__(16) float g_hs[(size_t)BB * TT * HH];

// tree barrier state (monotonic counters; reset by k_init each launch)
__device__ unsigned g_grp[32];
__device__ unsigned g_root;
__device__ unsigned g_gen;

// ---------------- math ----------------
__device__ __forceinline__ float tanh_fast(float x) {
    float y;
    asm("tanh.approx.f32 %0, %1;" : "=f"(y) : "f"(x));
    return y;
}
__device__ __forceinline__ float tanh_acc(float x) {
    float a = fabsf(x);
    float e = __expf(-2.0f * a);
    float r = __fdividef(1.0f - e, 1.0f + e);
    return copysignf(r, x);
}
__device__ __forceinline__ float sigm(float x) {
    return __fdividef(1.0f, 1.0f + __expf(-x));
}

// two-level tree grid barrier: 32 groups of 16 CTAs, root counts 32 groups
__device__ __forceinline__ void gsync(unsigned& my) {
    __syncthreads();
    my++;
    if (threadIdx.x == 0) {
        __threadfence();
        if ((atomicAdd(&g_grp[blockIdx.x & 31], 1u) & 15u) == 15u) {
            if ((atomicAdd(&g_root, 1u) & 31u) == 31u) {
                atomicAdd(&g_gen, 1u);
            }
        }
        while (*(volatile unsigned*)&g_gen < my) { __nanosleep(32); }
        __threadfence();
    }
    __syncthreads();
}

// ---------------- prep ----------------
// fused: weight permute + WgenT + embT  (grid 10240 x 256)
__global__ void k_prep_all(const float* __restrict__ W_ih, const float* __restrict__ b_ih,
                           const float* __restrict__ W_hh, const float* __restrict__ b_hh,
                           const float* __restrict__ Wgen,
                           const int* __restrict__ text, const float* __restrict__ emb_table) {
    int idx = blockIdx.x * 256 + threadIdx.x;
    // Wt permute: [k][u*4+g]
    {
        int k = idx >> 11;
        int col = idx & (G4 - 1);
        int u = col >> 2;
        int g = col & 3;
        int row = g * HH + u;                  // PyTorch gate order i,f,g,o
        float v = (k < CC + EE) ? W_ih[(size_t)row * (CC + EE) + k]
                                : W_hh[(size_t)row * HH + (k - (CC + EE))];
        g_Wt[idx] = v;
        if (k == 0) g_bperm[col] = b_ih[row] + b_hh[row];
    }
    // embT
    if (idx < TT * EE * BB) {
        int b = idx & (BB - 1);
        int e = (idx >> 6) & (EE - 1);
        int t = idx >> 14;
        int tok = text[b * TT + t];
        g_embT[idx] = emb_table[(size_t)tok * EE + e];
    }
    // WgenT
    if (idx < HH * NC) {
        int k = idx / NC, n = idx - k * NC;
        g_WgenT[idx] = Wgen[(size_t)n * HH + k];
    }
}

// init state + barrier counters (runs every launch, before k_steps)
__global__ void k_init() {
    int i = blockIdx.x * 256 + threadIdx.x;
    if (i < BB * HH) { g_h[i] = 0.f; g_hT[i] = 0.f; g_cT[i] = 0.f; }
    if (i < 32) g_grp[i] = 0u;
    if (i == 0) { g_root = 0u; g_gen = 0u; }
}

// src_featT[b][h][l] = sum_c Wi2h[h][c] * src[b][l][c]  (bf16 output)
__global__ __launch_bounds__(256) void k_srcfeat(const float* __restrict__ src,
                                                 const float* __restrict__ Wi2h) {
    __shared__ __align__(16) float Wsh[16][68];
    __shared__ __align__(16) float Ssh[16][68];
    int l0 = blockIdx.x * 64;
    int h0 = blockIdx.y * 64;
    int b  = blockIdx.z;
    int tid = threadIdx.x;
    int r  = tid >> 2;
    int kq = (tid & 3) << 2;
    int th = tid & 15;
    int tl = tid >> 4;
    float acc[4][4];
#pragma unroll
    for (int i = 0; i < 4; i++)
#pragma unroll
        for (int j = 0; j < 4; j++) acc[i][j] = 0.f;

    const float* srow = src + ((size_t)b * LL + l0 + r) * CC;
    const float* wrow = Wi2h + (size_t)(h0 + r) * CC;

    for (int k0 = 0; k0 < CC; k0 += 16) {
        float4 w4 = *(const float4*)(wrow + k0 + kq);
        float4 s4 = *(const float4*)(srow + k0 + kq);
        Wsh[kq + 0][r] = w4.x; Wsh[kq + 1][r] = w4.y; Wsh[kq + 2][r] = w4.z; Wsh[kq + 3][r] = w4.w;
        Ssh[kq + 0][r] = s4.x; Ssh[kq + 1][r] = s4.y; Ssh[kq + 2][r] = s4.z; Ssh[kq + 3][r] = s4.w;
        __syncthreads();
#pragma unroll
        for (int kk = 0; kk < 16; kk++) {
            float4 a4 = *(const float4*)&Wsh[kk][th << 2];
            float4 b4 = *(const float4*)&Ssh[kk][tl << 2];
            float av[4] = {a4.x, a4.y, a4.z, a4.w};
            float bv[4] = {b4.x, b4.y, b4.z, b4.w};
#pragma unroll
            for (int i = 0; i < 4; i++)
#pragma unroll
                for (int j = 0; j < 4; j++) acc[i][j] += av[i] * bv[j];
        }
        __syncthreads();
    }
#pragma unroll
    for (int i = 0; i < 4; i++) {
        __nv_bfloat162 p0 = __floats2bfloat162_rn(acc[i][0], acc[i][1]);
        __nv_bfloat162 p1 = __floats2bfloat162_rn(acc[i][2], acc[i][3]);
        uint2 u;
        u.x = *(unsigned*)&p0;
        u.y = *(unsigned*)&p1;
        *(uint2*)&g_srcfT[((size_t)b * HH + h0 + (th << 2) + i) * LL + l0 + (tl << 2)] = u;
    }
}

// ---------------- persistent step-loop kernel (512 CTAs, 4/SM) ----------------
__global__ __launch_bounds__(256, 4) void k_steps(const float* __restrict__ src,
                                                  const float* __restrict__ Wh2h,
                                                  const float* __restrict__ bh2h,
                                                  const float* __restrict__ wscore) {
    __shared__ __align__(16) float sm[4096];   // 16 KB, reused per phase
    int bid = blockIdx.x;
    int tid = threadIdx.x;
    unsigned my = 0;

    for (int t = 0; t < TT; t++) {
        // ===== phase 1: proj[b][j] = Wh2h[j][:] . h[b][:] + bh2h[j] =====
        // 512 blocks: 32 j-tiles(16) x 16 b-tiles(4); warp handles 2 j rows
        {
            float* hsh = sm;                    // 4 x 512
            int j0 = (bid & 31) << 4;
            int b0 = (bid >> 5) << 2;
            for (int i = tid; i < 4 * HH; i += 256)
                hsh[i] = __ldcg(&g_h[(b0 + (i >> 9)) * HH + (i & 511)]);
            __syncthreads();
            int w = tid >> 5, lane = tid & 31;
#pragma unroll
            for (int jj = 0; jj < 2; jj++) {
                int j = j0 + w * 2 + jj;
                float wreg[16];
                const float* wr = Wh2h + (size_t)j * HH;
#pragma unroll
                for (int i = 0; i < 16; i++) wreg[i] = wr[lane + i * 32];
                float bj = bh2h[j];
#pragma unroll
                for (int bb = 0; bb < 4; bb++) {
                    float acc = 0.f;
#pragma unroll
                    for (int i = 0; i < 16; i++) acc += wreg[i] * hsh[bb * HH + lane + i * 32];
#pragma unroll
                    for (int o = 16; o; o >>= 1) acc += __shfl_xor_sync(0xFFFFFFFFu, acc, o);
                    if (lane == 0) g_proj[(b0 + bb) * HH + j] = acc + bj;
                }
            }
        }
        gsync(my);

        // ===== phase 2: score partials; 512 blocks (8 h-chunks(64) x 64 b) =====
        {
            float* psh = sm;          // 64
            float* wsh = sm + 64;     // 64
            int hc = bid >> 6, b = bid & 63;
            int h0 = hc << 6;
            if (tid < 64) {
                psh[tid] = __ldcg(&g_proj[(b << 9) + h0 + tid]);
                wsh[tid] = wscore[h0 + tid];
            }
            __syncthreads();
            const __nv_bfloat16* sf = g_srcfT + ((size_t)b * HH + h0) * LL;
            // pass A: l = tid (0..255), all 64 h
            float lgA = 0.f;
#pragma unroll 8
            for (int h = 0; h < 64; h++)
                lgA += tanh_fast(__bfloat162float(sf[(size_t)h * LL + tid]) + psh[h]) * wsh[h];
            // pass B: l = 256 + (tid>>1), half h-range per thread, pair-combined
            int lB = 256 + (tid >> 1);
            int hb = (tid & 1) << 5;
            float lgB = 0.f;
#pragma unroll 8
            for (int i = 0; i < 32; i++) {
                int h = hb + i;
                lgB += tanh_fast(__bfloat162float(sf[(size_t)h * LL + lB]) + psh[h]) * wsh[h];
            }
            lgB += __shfl_xor_sync(0xFFFFFFFFu, lgB, 1);
            float* lp = g_lgp + (hc * BB + b) * LL;
            lp[tid] = lgA;
            if ((tid & 1) == 0) lp[lB] = lgB;
        }
        gsync(my);

        // ===== phase 3: softmax + context; 512 blocks (8 c-chunks(64) x 64 b) =====
        {
            float* lg    = sm;          // 384
            float* alpha = sm + 384;    // 384
            float* red   = sm + 768;    // 8
            float* bcv   = sm + 776;    // 2
            float* psum  = sm + 784;    // 256
            int cc = bid >> 6, b = bid & 63;
            const float* lp = g_lgp + b * LL;
            for (int l = tid; l < LL; l += 256) {
                float v = 0.f;
#pragma unroll
                for (int p = 0; p < 8; p++) v += __ldcg(lp + p * BB * LL + l);
                lg[l] = v;
            }
            __syncthreads();
            float m = lg[tid];
            if (tid < 128) m = fmaxf(m, lg[tid + 256]);
#pragma unroll
            for (int o = 16; o; o >>= 1) m = fmaxf(m, __shfl_xor_sync(0xFFFFFFFFu, m, o));
            if ((tid & 31) == 0) red[tid >> 5] = m;
            __syncthreads();
            if (tid == 0) {
                float mm = red[0];
#pragma unroll
                for (int i = 1; i < 8; i++) mm = fmaxf(mm, red[i]);
                bcv[0] = mm;
            }
            __syncthreads();
            float mx = bcv[0];
            float s = 0.f;
            for (int l = tid; l < LL; l += 256) {
                float e = __expf(lg[l] - mx);
                alpha[l] = e;
                s += e;
            }
#pragma unroll
            for (int o = 16; o; o >>= 1) s += __shfl_xor_sync(0xFFFFFFFFu, s, o);
            if ((tid & 31) == 0) red[tid >> 5] = s;
            __syncthreads();
            if (tid == 0) {
                float ss = 0.f;
#pragma unroll
                for (int i = 0; i < 8; i++) ss += red[i];
                bcv[1] = ss;
            }
            __syncthreads();
            float inv = __fdividef(1.f, bcv[1]);
            // context: 64 c's, 4-way l-split (96 l per thread)
            int c = (cc << 6) + (tid & 63);
            int lb = (tid >> 6) * 96;
            const float* sp = src + (size_t)b * LL * CC + (size_t)lb * CC + c;
            float acc = 0.f;
#pragma unroll 8
            for (int l = 0; l < 96; l++) acc += alpha[lb + l] * __ldcg(&sp[(size_t)l * CC]);
            psum[tid] = acc;
            __syncthreads();
            if (tid < 64)
                g_X[c * BB + b] = (psum[tid] + psum[tid + 64] + psum[tid + 128] + psum[tid + 192]) * inv;
        }
        gsync(my);

        // ===== phase 4: gate GEMM partials; 512 blocks (32 m-tiles(64) x 16 k-slices) =====
        {
            float (*Wsh)[64] = (float (*)[64])sm;              // 16x64
            float (*Xsh)[64] = (float (*)[64])(sm + 1024);     // 16x64
            int mt = bid & 31, ks = bid >> 5;
            int m0 = mt << 6;
            int k0b = ks * KSLICE;
            int tx = tid & 15;
            int ty = tid >> 4;
            int srow = tid >> 4;
            int scol = (tid & 15) << 2;
            float acc[4][4];
#pragma unroll
            for (int i = 0; i < 4; i++)
#pragma unroll
                for (int j = 0; j < 4; j++) acc[i][j] = 0.f;

            for (int kc = 0; kc < KSLICE; kc += 16) {
                int k0 = k0b + kc;
                *(float4*)&Wsh[srow][scol] =
                    *(const float4*)(g_Wt + (size_t)(k0 + srow) * G4 + m0 + scol);
                int r = k0 + srow;
                const float* xr = (r < CC) ? (g_X + r * BB)
                                : (r < CC + EE) ? (g_embT + ((size_t)t * EE + (r - CC)) * BB)
                                                : (g_hT + (r - CC - EE) * BB);
                *(float4*)&Xsh[srow][scol] = __ldcg((const float4*)(xr + scol));
                __syncthreads();
#pragma unroll
                for (int kk = 0; kk < 16; kk++) {
                    float4 a4 = *(const float4*)&Wsh[kk][ty << 2];
                    float4 b4 = *(const float4*)&Xsh[kk][tx << 2];
                    float av[4] = {a4.x, a4.y, a4.z, a4.w};
                    float bv[4] = {b4.x, b4.y, b4.z, b4.w};
#pragma unroll
                    for (int i = 0; i < 4; i++)
#pragma unroll
                        for (int j = 0; j < 4; j++) acc[i][j] += av[i] * bv[j];
                }
                __syncthreads();
            }
            float* op = g_gp + ((size_t)ks * G4 + m0 + (ty << 2)) * BB + (tx << 2);
#pragma unroll
            for (int i = 0; i < 4; i++)
                *(float4*)(op + (size_t)i * BB) =
                    make_float4(acc[i][0], acc[i][1], acc[i][2], acc[i][3]);
        }
        gsync(my);

        // ===== phase 5: cell update; 512 blocks x 64 (u,b), 4-way partial split =====
        {
            float4* cpart = (float4*)sm;          // 256 float4
            int o = tid & 63;
            int part = tid >> 6;                  // 0..3
            int idx = bid * 64 + o;               // 0..32767
            int b = idx & (BB - 1);
            int u = idx >> 6;
            const float* gp = g_gp + ((size_t)(u << 2)) * BB + b;
            float a0 = 0.f, a1 = 0.f, a2 = 0.f, a3 = 0.f;
#pragma unroll
            for (int ks = 0; ks < 4; ks++) {
                const float* p = gp + (size_t)(part * 4 + ks) * G4 * BB;
                a0 += __ldcg(p);
                a1 += __ldcg(p + BB);
                a2 += __ldcg(p + 2 * BB);
                a3 += __ldcg(p + 3 * BB);
            }
            cpart[tid] = make_float4(a0, a1, a2, a3);
            __syncthreads();
            if (part == 0) {
                float4 q1 = cpart[tid + 64];
                float4 q2 = cpart[tid + 128];
                float4 q3 = cpart[tid + 192];
                float4 bias = *(const float4*)&g_bperm[u << 2];
                a0 += q1.x + q2.x + q3.x + bias.x;
                a1 += q1.y + q2.y + q3.y + bias.y;
                a2 += q1.z + q2.z + q3.z + bias.z;
                a3 += q1.w + q2.w + q3.w + bias.w;
                float ig = sigm(a0);
                float fg = sigm(a1);
                float gg = tanh_acc(a2);
                float og = sigm(a3);
                int uc = u * BB + b;
                float cn = fg * __ldcg(&g_cT[uc]) + ig * gg;
                float hn = og * tanh_acc(cn);
                g_cT[uc] = cn;
                g_hT[uc] = hn;
                g_h[b * HH + u] = hn;
                __stcs(&g_hs[((size_t)(b * TT + t)) * HH + u], hn);
            }
        }
        gsync(my);
    }
}

// final: probs[m][n] = hs[m][:] . WgenT[:][n] + bgen[n]
__global__ __launch_bounds__(256) void k_out(const float* __restrict__ bgen,
                                             float* __restrict__ out) {
    __shared__ __align__(16) float Ash[16][68];
    __shared__ __align__(16) float Bsh[16][68];
    int m0 = blockIdx.x * 64;
    int n0 = blockIdx.y * 64;
    int tid = threadIdx.x;
    int r  = tid >> 2;
    int kq = (tid & 3) << 2;
    int bkk = tid >> 4;
    int nq  = (tid & 15) << 2;
    int tm = tid & 15;
    int tn = tid >> 4;
    float acc[4][4];
#pragma unroll
    for (int i = 0; i < 4; i++)
#pragma unroll
        for (int j = 0; j < 4; j++) acc[i][j] = 0.f;

    for (int k0 = 0; k0 < HH; k0 += 16) {
        float4 a4 = *(const float4*)&g_hs[(size_t)(m0 + r) * HH + k0 + kq];
        Ash[kq + 0][r] = a4.x; Ash[kq + 1][r] = a4.y; Ash[kq + 2][r] = a4.z; Ash[kq + 3][r] = a4.w;
#pragma unroll
        for (int j = 0; j < 4; j++) {
            int n = n0 + nq + j;
            Bsh[bkk][nq + j] = (n < NC) ? g_WgenT[(size_t)(k0 + bkk) * NC + n] : 0.f;
        }
        __syncthreads();
#pragma unroll
        for (int kk = 0; kk < 16; kk++) {
            float4 av4 = *(const float4*)&Ash[kk][tm << 2];
            float4 bv4 = *(const float4*)&Bsh[kk][tn << 2];
            float av[4] = {av4.x, av4.y, av4.z, av4.w};
            float bv[4] = {bv4.x, bv4.y, bv4.z, bv4.w};
#pragma unroll
            for (int i = 0; i < 4; i++)
#pragma unroll
                for (int j = 0; j < 4; j++) acc[i][j] += av[i] * bv[j];
        }
        __syncthreads();
    }
#pragma unroll
    for (int i = 0; i < 4; i++) {
        int m = m0 + (tm << 2) + i;
#pragma unroll
        for (int j = 0; j < 4; j++) {
            int n = n0 + (tn << 2) + j;
            if (n < NC) out[(size_t)m * NC + n] = acc[i][j] + bgen[n];
        }
    }
}

// ---------------- launch ----------------
extern "C" void kernel_launch(void* const* d_in, const int* in_sizes, int n_in,
                              void* d_out, int out_size) {
    const float* src       = (const float*)d_in[0];
    const int*   text      = (const int*)d_in[1];
    const float* emb_table = (const float*)d_in[2];
    const float* Wi2h      = (const float*)d_in[3];
    const float* Wh2h      = (const float*)d_in[4];
    const float* bh2h      = (const float*)d_in[5];
    const float* wscore    = (const float*)d_in[6];
    const float* W_ih      = (const float*)d_in[7];
    const float* b_ih      = (const float*)d_in[8];
    const float* W_hh      = (const float*)d_in[9];
    const float* b_hh      = (const float*)d_in[10];
    const float* Wgen      = (const float*)d_in[11];
    const float* bgen      = (const float*)d_in[12];
    float* out = (float*)d_out;
    (void)in_sizes; (void)n_in; (void)out_size;

    // order chosen so the ncu capture slot lands on k_steps
    k_prep_all<<<KX * G4 / 256, 256>>>(W_ih, b_ih, W_hh, b_hh, Wgen, text, emb_table);
    k_srcfeat<<<dim3(LL / 64, HH / 64, BB), 256>>>(src, Wi2h);
    k_init<<<128, 256>>>();
    k_steps<<<NBLK, 256>>>(src, Wh2h, bh2h, wscore);
    k_out<<<dim3(127, 4), 256>>>(bgen, out);
}